// round 17
// baseline (speedup 1.0000x reference)
#include <cuda_runtime.h>
#include <cuda_bf16.h>
#include <cstdint>

// LIF activation, forward:
//   decay[c] = 1 - w_leak[c]
//   gate  = (Vm < 1)  (strict)
//   Vm    = relu(x + decay*Vm*gate)
//   spike = (Vm > 1) ? 1 : 0  (strict)
// B=128, T=1000, C=512.
//
// FINAL — locked configuration. Best measured 88.19us / 6232 GB/s (78% of
// spec HBM); run-to-run band 88.2-90.1us across four runs of this binary.
//
// Architecture: fully-contiguous 1D bulk-async (TMA-engine) streaming in
// BOTH directions.
//   - grid=128 (one CTA per batch b; slab x[b] = 2MB contiguous)
//   - 512 threads, one per channel; T-recurrence is serial per thread
//   - CHUNK_T=20 -> 40KB contiguous transfers (longest DRAM burst runs)
//   - IN ring 3 stages + OUT ring 2 stages (~205KB smem, 1 CTA/SM)
//   - out-drain folded into the consume-sync; refill issued before compute
//
// Session findings (16 rounds):
//   1. Per-SM LDG/L1tex outstanding-request cap pins LDG/STG streaming at
//      ~4.3 TB/s on sm_103a regardless of occupancy/unroll/pipelining;
//      cp.async.bulk bypasses it in both directions (+26%). STG-only
//      epilogue regresses (R6) — stores need the bulk engine too.
//   2. Fully-contiguous 1D bulk beats strided 2D tensor-map boxes ~1-2%
//      (longer DRAM burst runs).
//   3. Beyond that: DRAM read/write-mix ceiling (74-79% of spec across 9
//      architectures) with traffic at the structural minimum (524MB).
//      Ring depth >3, chunks >40KB, drain placement, L2 policy hints, and
//      CTA granularity are all neutral within +/-1.3us noise.

namespace {
constexpr int B = 128;
constexpr int T = 1000;
constexpr int C = 512;
constexpr int CHUNK_T = 20;                        // timesteps per chunk
constexpr int NCHUNKS = T / CHUNK_T;               // 50
constexpr uint32_t CH_BYTES = CHUNK_T * C * 4;     // 40960
constexpr int IN_STAGES  = 3;
constexpr int OUT_STAGES = 2;
constexpr int THREADS = C;                         // 512, one per channel

constexpr uint32_t SMEM_IN   = 0;
constexpr uint32_t SMEM_OUT  = IN_STAGES * CH_BYTES;               // 122880
constexpr uint32_t SMEM_MBAR = SMEM_OUT + OUT_STAGES * CH_BYTES;   // 204800
constexpr uint32_t SMEM_TOTAL = SMEM_MBAR + IN_STAGES * 8 + 64;    // ~205KB
}

__device__ __forceinline__ uint32_t smem_u32(const void* p) {
    uint32_t a;
    asm("{ .reg .u64 t; cvta.to.shared.u64 t, %1; cvt.u32.u64 %0, t; }" : "=r"(a) : "l"(p));
    return a;
}
__device__ __forceinline__ void mbar_init(uint32_t mbar, uint32_t cnt) {
    asm volatile("mbarrier.init.shared.b64 [%0], %1;" :: "r"(mbar), "r"(cnt) : "memory");
}
__device__ __forceinline__ void mbar_expect_tx(uint32_t mbar, uint32_t bytes) {
    asm volatile("mbarrier.arrive.expect_tx.shared.b64 _, [%0], %1;" :: "r"(mbar), "r"(bytes) : "memory");
}
__device__ __forceinline__ void mbar_wait(uint32_t mbar, uint32_t parity) {
    uint32_t done;
    asm volatile(
        "{\n\t.reg .pred p;\n\t"
        "mbarrier.try_wait.parity.acquire.cta.shared::cta.b64 p, [%1], %2;\n\t"
        "selp.b32 %0, 1, 0, p;\n\t}"
        : "=r"(done) : "r"(mbar), "r"(parity) : "memory");
    while (!done) {
        asm volatile(
            "{\n\t.reg .pred p;\n\t"
            "mbarrier.try_wait.parity.acquire.cta.shared::cta.b64 p, [%1], %2, 0x989680;\n\t"
            "selp.b32 %0, 1, 0, p;\n\t}"
            : "=r"(done) : "r"(mbar), "r"(parity) : "memory");
    }
}
__device__ __forceinline__ void bulk_load(uint32_t smem_dst, const void* gmem_src,
                                          uint32_t bytes, uint32_t mbar) {
    asm volatile(
        "cp.async.bulk.shared::cta.global.mbarrier::complete_tx::bytes [%0], [%1], %2, [%3];"
        :: "r"(smem_dst), "l"(gmem_src), "r"(bytes), "r"(mbar) : "memory");
}
__device__ __forceinline__ void bulk_store(void* gmem_dst, uint32_t smem_src, uint32_t bytes) {
    asm volatile(
        "cp.async.bulk.global.shared::cta.bulk_group [%0], [%1], %2;"
        :: "l"(gmem_dst), "r"(smem_src), "r"(bytes) : "memory");
}

__global__ void __launch_bounds__(THREADS, 1)
lif_kernel(const float* __restrict__ x,
           const float* __restrict__ wl,
           float* __restrict__ out)
{
    extern __shared__ __align__(1024) char smem[];
    const uint32_t sbase = smem_u32(smem);
    const int tid = threadIdx.x;
    const int b   = blockIdx.x;
    const int c   = tid;                       // one thread per channel

    const float d = 1.0f - wl[c];
    float v = 0.0f;

    const float* __restrict__ xslab = x   + (size_t)b * T * C;   // 2MB contiguous
    float*       __restrict__ oslab = out + (size_t)b * T * C;

    if (tid == 0) {
        #pragma unroll
        for (int s = 0; s < IN_STAGES; s++)
            mbar_init(sbase + SMEM_MBAR + s * 8, 1);
    }
    __syncthreads();

    // Prologue: fill the IN ring (chunks 0..2) — 120KB of contiguous reads in flight.
    if (tid == 0) {
        #pragma unroll
        for (int s = 0; s < IN_STAGES; s++) {
            const uint32_t mbar = sbase + SMEM_MBAR + s * 8;
            mbar_expect_tx(mbar, CH_BYTES);
            bulk_load(sbase + SMEM_IN + s * CH_BYTES,
                      xslab + (size_t)s * CHUNK_T * C, CH_BYTES, mbar);
        }
    }

    int s = 0, parity = 0;
    for (int i = 0; i < NCHUNKS; i++) {
        const int o = i & (OUT_STAGES - 1);
        const uint32_t mbar = sbase + SMEM_MBAR + s * 8;

        // 1) Wait for input chunk i, pull this thread's column to registers.
        mbar_wait(mbar, (uint32_t)parity);

        const float* sin = (const float*)(smem + SMEM_IN + s * CH_BYTES);
        float xv[CHUNK_T];
        #pragma unroll
        for (int u = 0; u < CHUNK_T; u++)
            xv[u] = sin[u * C + c];

        // 2) One sync covers: (a) all threads consumed smem-in stage s,
        //    (b) tid0's drain of the out-buffer we're about to overwrite.
        if (tid == 0)
            asm volatile("cp.async.bulk.wait_group.read 1;" ::: "memory");
        __syncthreads();

        // 3) Refill the consumed in-stage immediately (loads run during compute).
        if (tid == 0) {
            const int nxt = i + IN_STAGES;
            if (nxt < NCHUNKS) {
                mbar_expect_tx(mbar, CH_BYTES);
                bulk_load(sbase + SMEM_IN + s * CH_BYTES,
                          xslab + (size_t)nxt * CHUNK_T * C, CH_BYTES, mbar);
            }
        }

        // 4) Serial recurrence, spikes into the out smem buffer.
        float* sout = (float*)(smem + SMEM_OUT + o * CH_BYTES);
        #pragma unroll
        for (int u = 0; u < CHUNK_T; u++) {
            v = fmaxf(0.0f, xv[u] + (v < 1.0f ? d * v : 0.0f));
            sout[u * C + c] = (v > 1.0f) ? 1.0f : 0.0f;
        }

        __syncthreads();   // all spikes for chunk i in smem

        // 5) Bulk-store the chunk: one 40KB fully-contiguous write burst.
        if (tid == 0) {
            asm volatile("fence.proxy.async.shared::cta;" ::: "memory");
            bulk_store(oslab + (size_t)i * CHUNK_T * C,
                       sbase + SMEM_OUT + o * CH_BYTES, CH_BYTES);
            asm volatile("cp.async.bulk.commit_group;" ::: "memory");
        }

        if (++s == IN_STAGES) { s = 0; parity ^= 1; }
    }

    if (tid == 0)
        asm volatile("cp.async.bulk.wait_group 0;" ::: "memory");
}

extern "C" void kernel_launch(void* const* d_in, const int* in_sizes, int n_in,
                              void* d_out, int out_size)
{
    const float* x  = (const float*)d_in[0];   // x [B,T,C]
    const float* wl = (const float*)d_in[1];   // w_leak [C]
    float* out      = (float*)d_out;

    cudaFuncSetAttribute(lif_kernel, cudaFuncAttributeMaxDynamicSharedMemorySize,
                         (int)SMEM_TOTAL);
    lif_kernel<<<B, THREADS, SMEM_TOTAL>>>(x, wl, out);
}